// round 13
// baseline (speedup 1.0000x reference)
#include <cuda_runtime.h>
#include <cstddef>

// Problem constants (B=64, T=2048, J=24, C=4*J+3=99)
#define NB 64
#define NT 2048
#define NJ 24
#define NC 99
#define TPB 128
#define GX (NT / TPB)          // 16
#define NBLK (GX * NB)         // 1024 partial sums
#define NSTAGE 4               // pipeline depth in stages
#define JPS 2                  // joints per stage
#define NST (NJ / JPS)         // 12 stages of work

__device__ float g_partials[NBLK];
__device__ unsigned int g_count = 0;

// ---------------- packed f32x2 helpers (Blackwell sm_100a) ----------------
typedef unsigned long long f2;

__device__ __forceinline__ f2 f2pk(float lo, float hi) {
    f2 r; asm("mov.b64 %0, {%1, %2};" : "=l"(r) : "f"(lo), "f"(hi)); return r;
}
__device__ __forceinline__ void f2un(f2 v, float& lo, float& hi) {
    asm("mov.b64 {%0, %1}, %2;" : "=f"(lo), "=f"(hi) : "l"(v));
}
__device__ __forceinline__ f2 f2add(f2 a, f2 b) {
    f2 r; asm("add.rn.f32x2 %0, %1, %2;" : "=l"(r) : "l"(a), "l"(b)); return r;
}
__device__ __forceinline__ f2 f2neg(f2 a) {
    f2 r; asm("xor.b64 %0, %1, 0x8000000080000000;" : "=l"(r) : "l"(a)); return r;
}
__device__ __forceinline__ f2 f2sub(f2 a, f2 b) { return f2add(a, f2neg(b)); }
__device__ __forceinline__ f2 f2mul(f2 a, f2 b) {
    f2 r; asm("mul.rn.f32x2 %0, %1, %2;" : "=l"(r) : "l"(a), "l"(b)); return r;
}
__device__ __forceinline__ f2 f2fma(f2 a, f2 b, f2 c) {
    f2 r; asm("fma.rn.f32x2 %0, %1, %2, %3;" : "=l"(r) : "l"(a), "l"(b), "l"(c)); return r;
}
__device__ __forceinline__ float frcp(float x) {
    float r; asm("rcp.approx.f32 %0, %1;" : "=f"(r) : "f"(x)); return r;
}

__device__ __forceinline__ float warp_sum(float v) {
#pragma unroll
    for (int o = 16; o > 0; o >>= 1) v += __shfl_down_sync(0xffffffffu, v, o);
    return v;
}

// quat->rotmat on a packed (Y,X) pair. q[4], m[9] all f32x2.
__device__ __forceinline__ void quat2mat2(const f2 q[4], f2 m[9]) {
    const f2 w = q[0], x = q[1], y = q[2], z = q[3];
    const f2 xx = f2mul(x, x), yy = f2mul(y, y), zz = f2mul(z, z);
    const f2 xy = f2mul(x, y), xz = f2mul(x, z), yz = f2mul(y, z);
    const f2 wx = f2mul(w, x), wy = f2mul(w, y), wz = f2mul(w, z);
    const f2 n  = f2fma(w, w, f2add(f2add(xx, yy), zz));
    float nl, nh; f2un(n, nl, nh);
    const float sl = 2.0f * frcp(nl), sh = 2.0f * frcp(nh);
    const f2 s   = f2pk(sl, sh);
    const f2 ns  = f2pk(-sl, -sh);
    const f2 one = f2pk(1.0f, 1.0f);
    m[0] = f2fma(ns, f2add(yy, zz), one);
    m[1] = f2mul(s,  f2sub(xy, wz));
    m[2] = f2mul(s,  f2add(xz, wy));
    m[3] = f2mul(s,  f2add(xy, wz));
    m[4] = f2fma(ns, f2add(xx, zz), one);
    m[5] = f2mul(s,  f2sub(yz, wx));
    m[6] = f2mul(s,  f2sub(xz, wy));
    m[7] = f2mul(s,  f2add(yz, wx));
    m[8] = f2fma(ns, f2add(xx, yy), one);
}

__device__ __forceinline__ void mat3mul2(const f2 a[9], const f2 b[9], f2 c[9]) {
#pragma unroll
    for (int r = 0; r < 3; r++)
#pragma unroll
        for (int cc = 0; cc < 3; cc++)
            c[r * 3 + cc] = f2fma(a[r * 3 + 0], b[0 * 3 + cc],
                            f2fma(a[r * 3 + 1], b[1 * 3 + cc],
                            f2mul(a[r * 3 + 2], b[2 * 3 + cc])));
}

__device__ __forceinline__ void cp16(unsigned int dst_smem, const float* src) {
    asm volatile("cp.async.cg.shared.global [%0], [%1], 16;"
                 :: "r"(dst_smem), "l"(src));
}
__device__ __forceinline__ void cp_commit() {
    asm volatile("cp.async.commit_group;");
}
__device__ __forceinline__ void cp_wait2() {
    asm volatile("cp.async.wait_group 2;");
}

// Issue one stage into buffer buf, then advance the 4 source pointers by one
// stage stride (8 channel rows). Strictly sequential stage issuance.
__device__ __forceinline__ void issue_stage(
    unsigned int stg_base, int buf,
    const float* cur[4], const unsigned int off[4])
{
#pragma unroll
    for (int c = 0; c < 4; c++) {
        cp16(stg_base + (unsigned int)(buf * 8192) + off[c], cur[c]);
        cur[c] += (size_t)(4 * JPS) * NT;
    }
}

__global__ void __launch_bounds__(TPB) motion_loss_kernel(
    const float* __restrict__ Ym, const float* __restrict__ Xm,
    const float* __restrict__ Yt, const float* __restrict__ Xt,
    const float* __restrict__ jw, float* __restrict__ out)
{
    // Stage buffer: [stage][row 0-15][t 0-127].
    // Rows 0-7  = Y quat channels 8s..8s+7 (joints 2s, 2s+1)
    // Rows 8-15 = X quat channels 8s..8s+7.  8 KB per stage.
    __shared__ float stg[NSTAGE][8 * JPS][TPB];
    __shared__ float sw[NJ];
    __shared__ f2    so[NJ * 3];     // packed (Yt, Xt) offsets for this batch
    __shared__ float red[TPB / 32];
    __shared__ bool  is_last;

    const int b   = blockIdx.y;
    const int t0  = blockIdx.x * TPB;
    const int tid = threadIdx.x;

    const float* yb0 = Ym + (size_t)b * NC * NT + t0;   // + channel*NT + t
    const float* xb0 = Xm + (size_t)b * NC * NT + t0;

    // TOPOLOGY = {-1,0,0,0,1,2,3,4,5,6,7,8,9,9,9,12,13,14,16,17,18,19,20,21}
    // 3-slot breadth layout (identical to the champion kernels).
    constexpr int SLOT[NJ]  = {0,1,2,0,1,2,0,1,2,0,-1,-1,1,2,0,-1,1,2,0,1,2,0,-1,-1};
    constexpr int PSLOT[NJ] = {-1,0,0,0,1,2,0,1,2,0,1,2,0,0,0,1,2,0,1,2,0,1,2,0};

    const unsigned int stg_base = (unsigned int)__cvta_generic_to_shared(&stg[0][0][0]);

    // Per-thread cp.async source pointers and smem offsets (computed ONCE).
    // Segment c covers rows 4c..4c+3: seg = c*128 + tid, row = seg>>5, col = seg&31.
    const float* cur[4];
    unsigned int off[4];
#pragma unroll
    for (int c = 0; c < 4; c++) {
        const int seg = c * TPB + tid;        // 0..511
        const int row = seg >> 5;             // 0..15
        const int col = seg & 31;             // 16B unit within 512B row
        const float* base = (row < 8) ? yb0 : xb0;
        cur[c] = base + (size_t)(row & 7) * NT + col * 4;   // stage 0 source
        off[c] = (unsigned int)(row * 512 + col * 16);
    }

    // Prologue: stages 0..NSTAGE-2 in flight (group index == stage index).
#pragma unroll
    for (int s = 0; s < NSTAGE - 1; s++) {
        issue_stage(stg_base, s, cur, off);
        cp_commit();
    }

    if (tid < NJ) sw[tid] = jw[tid];
    if (tid < NJ * 3) so[tid] = f2pk(Yt[b * NJ * 3 + tid], Xt[b * NJ * 3 + tid]);

    float lrot = 0.0f, lfk = 0.0f;

    f2 Ts[3][9];
    f2 Rs[3][3];

#pragma unroll
    for (int s = 0; s < NST; s++) {
        // Stage s resident; barrier also guarantees all warps finished
        // reading buffer (s-1)%NSTAGE before it is refilled below.
        cp_wait2();
        __syncthreads();

        if (s + NSTAGE - 1 < NST)
            issue_stage(stg_base, (s + NSTAGE - 1) % NSTAGE, cur, off);
        cp_commit();                               // unconditional: group==stage

        const int buf = s % NSTAGE;

#pragma unroll
        for (int p = 0; p < JPS; p++) {
            const int i  = JPS * s + p;            // joint index
            const float wj = sw[i];

            f2 q[4];
            float rd = 0.0f;
#pragma unroll
            for (int k = 0; k < 4; k++) {
                const float a = stg[buf][4 * p + k][tid];
                const float c = stg[buf][8 + 4 * p + k][tid];
                rd += fabsf(a - c);
                q[k] = f2pk(a, c);
            }
            lrot += wj * rd;

            f2 m[9];
            quat2mat2(q, m);

            f2 c[9];
            if (i == 0) {
#pragma unroll
                for (int e = 0; e < 9; e++) c[e] = m[e];
            } else {
                mat3mul2(Ts[PSLOT[i]], m, c);
            }

            f2 r[3];
#pragma unroll
            for (int rr = 0; rr < 3; rr++)
                r[rr] = f2fma(c[rr * 3 + 2], so[i * 3 + 2],
                        f2fma(c[rr * 3 + 1], so[i * 3 + 1],
                        f2mul(c[rr * 3 + 0], so[i * 3 + 0])));
            if (i > 0) {
                const int ps = PSLOT[i];
#pragma unroll
                for (int rr = 0; rr < 3; rr++) r[rr] = f2add(r[rr], Rs[ps][rr]);
            }

            float fkd = 0.0f;
#pragma unroll
            for (int rr = 0; rr < 3; rr++) {
                float ylo, xhi; f2un(r[rr], ylo, xhi);
                fkd += fabsf(ylo - xhi);
            }
            lfk += wj * fkd;

            if (SLOT[i] >= 0) {
                const int sl = SLOT[i];
#pragma unroll
                for (int e = 0; e < 9; e++) Ts[sl][e] = c[e];
#pragma unroll
                for (int rr = 0; rr < 3; rr++) Rs[sl][rr] = r[rr];
            }
        }
    }

    float lpos = 0.0f;
#pragma unroll
    for (int d = 0; d < 3; d++)
        lpos += fabsf(yb0[(size_t)(4 * NJ + d) * NT + tid] -
                      xb0[(size_t)(4 * NJ + d) * NT + tid]);

    // loss = B1*sum_rot/(B*T*J*4) + B2*sum_fk/(B*T*J*3) + sum_pos/(B*T*3)
    const float CR = 1.0f / (64.0f * 2048.0f * 24.0f * 4.0f);
    const float CF = 1.0f / (64.0f * 2048.0f * 24.0f * 3.0f);
    const float CP = 1.0f / (64.0f * 2048.0f * 3.0f);
    float v = lrot * CR + lfk * CF + lpos * CP;

    // ---- block reduction ----
    v = warp_sum(v);
    if ((tid & 31) == 0) red[tid >> 5] = v;
    __syncthreads();
    if (tid == 0) {
        float s = 0.0f;
#pragma unroll
        for (int wgi = 0; wgi < TPB / 32; wgi++) s += red[wgi];
        g_partials[blockIdx.y * GX + blockIdx.x] = s;
        __threadfence();
        const unsigned int old = atomicAdd(&g_count, 1u);
        is_last = (old == NBLK - 1);
    }
    __syncthreads();

    // ---- last block folds all partials (deterministic fixed-order sum) ----
    if (is_last) {
        float s = 0.0f;
#pragma unroll
        for (int k = 0; k < NBLK / TPB; k++) s += g_partials[tid + k * TPB];
        s = warp_sum(s);
        if ((tid & 31) == 0) red[tid >> 5] = s;
        __syncthreads();
        if (tid == 0) {
            float tot = 0.0f;
#pragma unroll
            for (int wgi = 0; wgi < TPB / 32; wgi++) tot += red[wgi];
            out[0] = tot;
            g_count = 0;   // reset for next graph replay
        }
    }
}

extern "C" void kernel_launch(void* const* d_in, const int* in_sizes, int n_in,
                              void* d_out, int out_size) {
    const float* Ym = (const float*)d_in[0];
    const float* Xm = (const float*)d_in[1];
    const float* Yt = (const float*)d_in[2];
    const float* Xt = (const float*)d_in[3];
    const float* jw = (const float*)d_in[4];

    dim3 grid(GX, NB);
    motion_loss_kernel<<<grid, TPB>>>(Ym, Xm, Yt, Xt, jw, (float*)d_out);
}

// round 15
// speedup vs baseline: 1.2458x; 1.2458x over previous
#include <cuda_runtime.h>
#include <cstddef>

// Problem constants (B=64, T=2048, J=24, C=4*J+3=99)
#define NB 64
#define NT 2048
#define NJ 24
#define NC 99
#define TPB 128
#define GX (NT / TPB)          // 16
#define NBLK (GX * NB)         // 1024 partial sums
#define NSTAGE 4               // pipeline depth in stages
#define JPS 2                  // joints per stage
#define NST (NJ / JPS)         // 12 stages of work

__device__ float g_partials[NBLK];
__device__ unsigned int g_count = 0;

// ---------------- packed f32x2 helpers (Blackwell sm_100a) ----------------
typedef unsigned long long f2;

__device__ __forceinline__ f2 f2pk(float lo, float hi) {
    f2 r; asm("mov.b64 %0, {%1, %2};" : "=l"(r) : "f"(lo), "f"(hi)); return r;
}
__device__ __forceinline__ void f2un(f2 v, float& lo, float& hi) {
    asm("mov.b64 {%0, %1}, %2;" : "=f"(lo), "=f"(hi) : "l"(v));
}
__device__ __forceinline__ f2 f2add(f2 a, f2 b) {
    f2 r; asm("add.rn.f32x2 %0, %1, %2;" : "=l"(r) : "l"(a), "l"(b)); return r;
}
__device__ __forceinline__ f2 f2neg(f2 a) {
    f2 r; asm("xor.b64 %0, %1, 0x8000000080000000;" : "=l"(r) : "l"(a)); return r;
}
__device__ __forceinline__ f2 f2sub(f2 a, f2 b) { return f2add(a, f2neg(b)); }
__device__ __forceinline__ f2 f2mul(f2 a, f2 b) {
    f2 r; asm("mul.rn.f32x2 %0, %1, %2;" : "=l"(r) : "l"(a), "l"(b)); return r;
}
__device__ __forceinline__ f2 f2fma(f2 a, f2 b, f2 c) {
    f2 r; asm("fma.rn.f32x2 %0, %1, %2, %3;" : "=l"(r) : "l"(a), "l"(b), "l"(c)); return r;
}
__device__ __forceinline__ float frcp(float x) {
    float r; asm("rcp.approx.f32 %0, %1;" : "=f"(r) : "f"(x)); return r;
}

__device__ __forceinline__ float warp_sum(float v) {
#pragma unroll
    for (int o = 16; o > 0; o >>= 1) v += __shfl_down_sync(0xffffffffu, v, o);
    return v;
}

// Hamilton product o = a ⊗ b (packed (Y,X) lanes). o must not alias a/b.
__device__ __forceinline__ void qmul2(const f2 a[4], const f2 b[4], f2 o[4]) {
    const f2 d = f2fma(a[1], b[1], f2fma(a[2], b[2], f2mul(a[3], b[3])));
    o[0] = f2sub(f2mul(a[0], b[0]), d);
    o[1] = f2fma(a[0], b[1], f2fma(a[1], b[0], f2fma(a[2], b[3], f2mul(f2neg(a[3]), b[2]))));
    o[2] = f2fma(a[0], b[2], f2fma(a[2], b[0], f2fma(a[3], b[1], f2mul(f2neg(a[1]), b[3]))));
    o[3] = f2fma(a[0], b[3], f2fma(a[3], b[0], f2fma(a[1], b[2], f2mul(f2neg(a[2]), b[1]))));
}

// r = rotate(off) by q with scale sa = 2/|q|^2:
//   r = off + sa * ( u×(u×off + w·off) ),  u = (q1,q2,q3), w = q0.
__device__ __forceinline__ void qrot2(const f2 q[4], const f2* __restrict__ off,
                                      f2 sa, f2 r[3]) {
    const f2 w = q[0], x = q[1], y = q[2], z = q[3];
    const f2 nx = f2neg(x), ny = f2neg(y), nz = f2neg(z);
    const f2 t0 = f2fma(w, off[0], f2fma(y, off[2], f2mul(nz, off[1])));
    const f2 t1 = f2fma(w, off[1], f2fma(z, off[0], f2mul(nx, off[2])));
    const f2 t2 = f2fma(w, off[2], f2fma(x, off[1], f2mul(ny, off[0])));
    const f2 c0 = f2fma(y, t2, f2mul(nz, t1));
    const f2 c1 = f2fma(z, t0, f2mul(nx, t2));
    const f2 c2 = f2fma(x, t1, f2mul(ny, t0));
    r[0] = f2fma(sa, c0, off[0]);
    r[1] = f2fma(sa, c1, off[1]);
    r[2] = f2fma(sa, c2, off[2]);
}

__device__ __forceinline__ void cp16(unsigned int dst_smem, const float* src) {
    asm volatile("cp.async.cg.shared.global [%0], [%1], 16;"
                 :: "r"(dst_smem), "l"(src));
}
__device__ __forceinline__ void cp_commit() {
    asm volatile("cp.async.commit_group;");
}
__device__ __forceinline__ void cp_wait2() {
    asm volatile("cp.async.wait_group 2;");
}

// Issue one stage into buffer buf, then advance the 4 source pointers by one
// stage stride (8 channel rows). Strictly sequential stage issuance.
__device__ __forceinline__ void issue_stage(
    unsigned int stg_base, int buf,
    const float* cur[4], const unsigned int off[4])
{
#pragma unroll
    for (int c = 0; c < 4; c++) {
        cp16(stg_base + (unsigned int)(buf * 8192) + off[c], cur[c]);
        cur[c] += (size_t)(4 * JPS) * NT;
    }
}

__global__ void __launch_bounds__(TPB) motion_loss_kernel(
    const float* __restrict__ Ym, const float* __restrict__ Xm,
    const float* __restrict__ Yt, const float* __restrict__ Xt,
    const float* __restrict__ jw, float* __restrict__ out)
{
    // Stage buffer: [stage][row 0-15][t 0-127].
    // Rows 0-7  = Y quat channels 8s..8s+7 (joints 2s, 2s+1)
    // Rows 8-15 = X quat channels 8s..8s+7.  8 KB per stage.
    __shared__ float stg[NSTAGE][8 * JPS][TPB];
    __shared__ float sw[NJ];
    __shared__ f2    so[NJ * 3];     // packed (Yt, Xt) offsets for this batch
    __shared__ float red[TPB / 32];
    __shared__ bool  is_last;

    const int b   = blockIdx.y;
    const int t0  = blockIdx.x * TPB;
    const int tid = threadIdx.x;

    const float* yb0 = Ym + (size_t)b * NC * NT + t0;   // + channel*NT + t
    const float* xb0 = Xm + (size_t)b * NC * NT + t0;

    // TOPOLOGY = {-1,0,0,0,1,2,3,4,5,6,7,8,9,9,9,12,13,14,16,17,18,19,20,21}
    // 3-slot breadth layout (identical to the champion kernels).
    constexpr int SLOT[NJ]  = {0,1,2,0,1,2,0,1,2,0,-1,-1,1,2,0,-1,1,2,0,1,2,0,-1,-1};
    constexpr int PSLOT[NJ] = {-1,0,0,0,1,2,0,1,2,0,1,2,0,0,0,1,2,0,1,2,0,1,2,0};

    const unsigned int stg_base = (unsigned int)__cvta_generic_to_shared(&stg[0][0][0]);

    // Per-thread cp.async source pointers and smem offsets (computed ONCE).
    const float* cur[4];
    unsigned int off[4];
#pragma unroll
    for (int c = 0; c < 4; c++) {
        const int seg = c * TPB + tid;        // 0..511
        const int row = seg >> 5;             // 0..15
        const int col = seg & 31;             // 16B unit within 512B row
        const float* base = (row < 8) ? yb0 : xb0;
        cur[c] = base + (size_t)(row & 7) * NT + col * 4;   // stage 0 source
        off[c] = (unsigned int)(row * 512 + col * 16);
    }

    // Prologue: stages 0..NSTAGE-2 in flight (group index == stage index).
#pragma unroll
    for (int s = 0; s < NSTAGE - 1; s++) {
        issue_stage(stg_base, s, cur, off);
        cp_commit();
    }

    if (tid < NJ) sw[tid] = jw[tid];
    if (tid < NJ * 3) so[tid] = f2pk(Yt[b * NJ * 3 + tid], Xt[b * NJ * 3 + tid]);

    float lrot = 0.0f, lfk = 0.0f;

    // Quaternion-chain FK state per slot: accumulated quat, scale 2/|q|^2, result.
    f2 Qs[3][4];
    f2 Ss[3];
    f2 Rs[3][3];

#pragma unroll
    for (int s = 0; s < NST; s++) {
        // Stage s resident; barrier also guarantees all warps finished
        // reading buffer (s-1)%NSTAGE before it is refilled below.
        cp_wait2();
        __syncthreads();

        if (s + NSTAGE - 1 < NST)
            issue_stage(stg_base, (s + NSTAGE - 1) % NSTAGE, cur, off);
        cp_commit();                               // unconditional: group==stage

        const int buf = s % NSTAGE;

#pragma unroll
        for (int p = 0; p < JPS; p++) {
            const int i  = JPS * s + p;            // joint index
            const float wj = sw[i];

            f2 q[4];
            float rd = 0.0f;
#pragma unroll
            for (int k = 0; k < 4; k++) {
                const float a = stg[buf][4 * p + k][tid];
                const float c = stg[buf][8 + 4 * p + k][tid];
                rd += fabsf(a - c);
                q[k] = f2pk(a, c);
            }
            lrot += wj * rd;

            // |q|^2 and its packed reciprocal
            const f2 nq = f2fma(q[0], q[0],
                          f2fma(q[1], q[1],
                          f2fma(q[2], q[2], f2mul(q[3], q[3]))));
            float nl, nh; f2un(nq, nl, nh);
            const f2 rnq = f2pk(frcp(nl), frcp(nh));

            f2 qa[4], sa, r[3];
            if (i == 0) {
#pragma unroll
                for (int e = 0; e < 4; e++) qa[e] = q[e];
                sa = f2add(rnq, rnq);               // 2/|q|^2
                qrot2(qa, &so[0], sa, r);
            } else {
                const int ps = PSLOT[i];
                qmul2(Qs[ps], q, qa);
                sa = f2mul(Ss[ps], rnq);            // 2/(|qp|^2 |q|^2)
                qrot2(qa, &so[i * 3], sa, r);
#pragma unroll
                for (int rr = 0; rr < 3; rr++) r[rr] = f2add(r[rr], Rs[ps][rr]);
            }

            float fkd = 0.0f;
#pragma unroll
            for (int rr = 0; rr < 3; rr++) {
                float ylo, xhi; f2un(r[rr], ylo, xhi);
                fkd += fabsf(ylo - xhi);
            }
            lfk += wj * fkd;

            if (SLOT[i] >= 0) {
                const int sl = SLOT[i];
#pragma unroll
                for (int e = 0; e < 4; e++) Qs[sl][e] = qa[e];
                Ss[sl] = sa;
#pragma unroll
                for (int rr = 0; rr < 3; rr++) Rs[sl][rr] = r[rr];
            }
        }
    }

    float lpos = 0.0f;
#pragma unroll
    for (int d = 0; d < 3; d++)
        lpos += fabsf(yb0[(size_t)(4 * NJ + d) * NT + tid] -
                      xb0[(size_t)(4 * NJ + d) * NT + tid]);

    // loss = B1*sum_rot/(B*T*J*4) + B2*sum_fk/(B*T*J*3) + sum_pos/(B*T*3)
    const float CR = 1.0f / (64.0f * 2048.0f * 24.0f * 4.0f);
    const float CF = 1.0f / (64.0f * 2048.0f * 24.0f * 3.0f);
    const float CP = 1.0f / (64.0f * 2048.0f * 3.0f);
    float v = lrot * CR + lfk * CF + lpos * CP;

    // ---- block reduction ----
    v = warp_sum(v);
    if ((tid & 31) == 0) red[tid >> 5] = v;
    __syncthreads();
    if (tid == 0) {
        float s = 0.0f;
#pragma unroll
        for (int wgi = 0; wgi < TPB / 32; wgi++) s += red[wgi];
        g_partials[blockIdx.y * GX + blockIdx.x] = s;
        __threadfence();
        const unsigned int old = atomicAdd(&g_count, 1u);
        is_last = (old == NBLK - 1);
    }
    __syncthreads();

    // ---- last block folds all partials (deterministic fixed-order sum) ----
    if (is_last) {
        float s = 0.0f;
#pragma unroll
        for (int k = 0; k < NBLK / TPB; k++) s += g_partials[tid + k * TPB];
        s = warp_sum(s);
        if ((tid & 31) == 0) red[tid >> 5] = s;
        __syncthreads();
        if (tid == 0) {
            float tot = 0.0f;
#pragma unroll
            for (int wgi = 0; wgi < TPB / 32; wgi++) tot += red[wgi];
            out[0] = tot;
            g_count = 0;   // reset for next graph replay
        }
    }
}

extern "C" void kernel_launch(void* const* d_in, const int* in_sizes, int n_in,
                              void* d_out, int out_size) {
    const float* Ym = (const float*)d_in[0];
    const float* Xm = (const float*)d_in[1];
    const float* Yt = (const float*)d_in[2];
    const float* Xt = (const float*)d_in[3];
    const float* jw = (const float*)d_in[4];

    dim3 grid(GX, NB);
    motion_loss_kernel<<<grid, TPB>>>(Ym, Xm, Yt, Xt, jw, (float*)d_out);
}